// round 6
// baseline (speedup 1.0000x reference)
#include <cuda_runtime.h>

// NeRF importance sampler — search-free formulation.
//   inputs : rays_o[N,3], rays_d[N,3], z_vals[N,64] (sorted), weights[N,64]
//   outputs: pts[N,192,3] | z_all[N,192] | z_samples[N,128]  (flat concat)
//
// One warp per ray, 8 warps/block. Because u_j = j/127 is a uniform grid,
// searchsorted(cdf, u_j, 'right') is inverted analytically: each cdf boundary m
// maps to B_m = min(ceil(127*cdf_m), 128) = first sample index at/above it.
// lo_j = 1 + #{m in 1..62 : B_m <= j}, computed for all 128 samples with a
// shared scatter-increment + one warp scan. The 64+128 merge then needs only
// integer ranks (B array) plus one float compare per element, and the
// zv-side / zs-side compares are exactly complementary (zs<zv vs zv<=zs),
// so the output positions always form a permutation.

#define NS   64
#define NI   128
#define NT   192
#define WPB  8
#define WST  704   // floats per warp scratch (2816 B, 16B-aligned multiples)

__global__ __launch_bounds__(256)
void importance_sampler_kernel(const float* __restrict__ rays_o,
                               const float* __restrict__ rays_d,
                               const float* __restrict__ z_vals,
                               const float* __restrict__ weights,
                               float* __restrict__ out_pts,    // [N,192,3]
                               float* __restrict__ out_zall,   // [N,192]
                               float* __restrict__ out_zs,     // [N,128]
                               int n_rays)
{
    __shared__ __align__(16) float sbuf[WPB][WST];

    const int warp = threadIdx.x >> 5;
    const int lane = threadIdx.x & 31;
    const int ray  = blockIdx.x * WPB + warp;
    if (ray >= n_rays) return;

    float* buf = sbuf[warp];
    float* zv  = buf;                  // [0,64)
    float* cdf = buf + 64;             // [64,127) used (63 entries)
    float* mid = buf + 128;            // [128,191) used (63 entries)
    float* zs  = buf + 192;            // [192,320)
    float* zal = buf + 320;            // [320,512)
    int*   Bar = (int*)(buf + 512);    // [512,576) : B[0..63]
    int*   dmk = (int*)(buf + 576);    // [576,704) : marker histogram[128]

    // ---- Phase 1: load z_vals + weights, build cdf and B ------------------
    const float2 z2 = ((const float2*)(z_vals + (size_t)ray * NS))[lane];
    ((float2*)zv)[lane] = z2;

    const float2 w2 = ((const float2*)(weights + (size_t)ray * NS))[lane];
    const float wnx = __shfl_down_sync(0xffffffffu, w2.x, 1);   // wrow[2l+2]

    // zero marker histogram (visible after the syncwarp below)
    ((int4*)dmk)[lane] = make_int4(0, 0, 0, 0);

    // w[j] = weights[j+1] + 1e-5, j = 0..61; lane l<31 owns j=2l (wa), 2l+1 (wb)
    float wa = 0.f, wb = 0.f;
    if (lane < 31) {
        wa = w2.y + 1e-5f;
        wb = wnx  + 1e-5f;
    }
    const float local = wa + wb;
    float s = local;
    #pragma unroll
    for (int off = 1; off < 32; off <<= 1) {
        float up = __shfl_up_sync(0xffffffffu, s, off);
        if (lane >= off) s += up;
    }
    const float inv_total = 1.0f / __shfl_sync(0xffffffffu, s, 31);
    const float excl = s - local;

    int b1 = 128, b2 = 128;
    if (lane < 31) {
        const float c1 = (excl + wa) * inv_total;     // cdf[2l+1]
        const float c2 = (excl + local) * inv_total;  // cdf[2l+2]
        cdf[2 * lane + 1] = c1;
        cdf[2 * lane + 2] = c2;
        b1 = min((int)ceilf(c1 * 127.0f), 128);
        b2 = min((int)ceilf(c2 * 127.0f), 128);
        Bar[2 * lane + 1] = b1;
        Bar[2 * lane + 2] = b2;
    } else {
        cdf[0]  = 0.f;
        Bar[0]  = 0;
        Bar[63] = 128;
    }

    // ---- Phase 2: z_mid[k] = 0.5*(zv[k]+zv[k+1]), k = 0..62 ---------------
    const float znx = __shfl_down_sync(0xffffffffu, z2.x, 1);   // zv[2l+2]
    mid[2 * lane] = 0.5f * (z2.x + z2.y);                       // mid[62] at l=31
    if (lane < 31) mid[2 * lane + 1] = 0.5f * (z2.y + znx);
    __syncwarp();

    // ---- markers: one increment at each boundary's first sample index -----
    if (lane < 31) {
        if (b1 < 128) atomicAdd(&dmk[b1], 1);
        if (b2 < 128) atomicAdd(&dmk[b2], 1);
    }
    __syncwarp();

    // ---- Phase 3: scan -> lo_j for samples j = 4*lane + r, then interp ----
    const int4 dv = ((const int4*)dmk)[lane];
    const int p0 = dv.x;
    const int p1 = p0 + dv.y;
    const int p2 = p1 + dv.z;
    const int p3 = p2 + dv.w;
    int run = p3;
    #pragma unroll
    for (int off = 1; off < 32; off <<= 1) {
        int up = __shfl_up_sync(0xffffffffu, run, off);
        if (lane >= off) run += up;
    }
    const int base = run - p3;
    const int los[4] = { base + p0 + 1, base + p1 + 1, base + p2 + 1, base + p3 + 1 };

    const int j0 = 4 * lane;
    float vv[4];
    #pragma unroll
    for (int r = 0; r < 4; r++) {
        const float u = (float)(j0 + r) * (1.0f / 127.0f);
        const int lo    = los[r];
        const int below = lo - 1;
        const int above = min(lo, 62);
        const float cb = cdf[below];
        float denom = cdf[above] - cb;
        if (denom < 1e-5f) denom = 1.0f;
        const float tt = (u - cb) / denom;
        const float mb = mid[below];
        vv[r] = fmaf(tt, mid[above] - mb, mb);
    }
    const float4 v4 = make_float4(vv[0], vv[1], vv[2], vv[3]);
    ((float4*)zs)[lane] = v4;
    ((float4*)(out_zs + (size_t)ray * NI))[lane] = v4;          // coalesced

    // zs-side merge: pos = j + lo + (zv[lo] <= v)  (zv[0..lo-1] < v < zv[lo+1])
    #pragma unroll
    for (int r = 0; r < 4; r++) {
        const int lo = los[r];
        const int cnt = lo + (zv[lo] <= vv[r] ? 1 : 0);
        zal[j0 + r + cnt] = vv[r];
    }
    __syncwarp();

    // ---- Phase 4: zv-side merge. pos_i = i + B[i-1] + #{j in [B[i-1],B[i]) :
    //      zs[j] < zv[i]}  (all samples with lo<=i-1 are < zv[i]; lo>=i+1 are >)
    #pragma unroll
    for (int t = 0; t < 2; t++) {
        const int i = 2 * lane + t;
        const float v = t ? z2.y : z2.x;
        const int bprev = (i == 0) ? 0 : Bar[i - 1];
        const int bcur  = Bar[i];
        int cnt = bprev;
        for (int j = bprev; j < bcur; j++)
            if (zs[j] < v) cnt++;
        zal[i + cnt] = v;
    }
    __syncwarp();

    // ---- Phase 5: direct pts + z_all output. Lane owns 4 consecutive points:
    //      1 LDS.128, 12 FMA, 3 STG.128 (stride 48B, all sectors fully written).
    const float ox = rays_o[3 * (size_t)ray + 0];
    const float oy = rays_o[3 * (size_t)ray + 1];
    const float oz = rays_o[3 * (size_t)ray + 2];
    const float dx = rays_d[3 * (size_t)ray + 0];
    const float dy = rays_d[3 * (size_t)ray + 1];
    const float dz = rays_d[3 * (size_t)ray + 2];

    float* optr  = out_pts  + (size_t)ray * (NT * 3);
    float* zaptr = out_zall + (size_t)ray * NT;

    #pragma unroll
    for (int t = 0; t < 2; t++) {
        if (t == 0 || lane < 16) {                 // 48 float4-groups of zal
            const int g = lane + 32 * t;           // group id: points 4g..4g+3
            const float4 z4 = ((const float4*)zal)[g];
            ((float4*)zaptr)[g] = z4;              // z_all out, coalesced

            float4 a, b, c;
            a.x = fmaf(dx, z4.x, ox); a.y = fmaf(dy, z4.x, oy); a.z = fmaf(dz, z4.x, oz);
            a.w = fmaf(dx, z4.y, ox);
            b.x = fmaf(dy, z4.y, oy); b.y = fmaf(dz, z4.y, oz);
            b.z = fmaf(dx, z4.z, ox); b.w = fmaf(dy, z4.z, oy);
            c.x = fmaf(dz, z4.z, oz);
            c.y = fmaf(dx, z4.w, ox); c.z = fmaf(dy, z4.w, oy); c.w = fmaf(dz, z4.w, oz);

            float4* dst = (float4*)(optr + 12 * g);   // 48B per lane-group
            dst[0] = a; dst[1] = b; dst[2] = c;
        }
    }
}

extern "C" void kernel_launch(void* const* d_in, const int* in_sizes, int n_in,
                              void* d_out, int out_size)
{
    const float* rays_o  = (const float*)d_in[0];
    const float* rays_d  = (const float*)d_in[1];
    const float* z_vals  = (const float*)d_in[2];
    const float* weights = (const float*)d_in[3];

    const int n_rays = in_sizes[0] / 3;

    float* out_pts  = (float*)d_out;
    float* out_zall = out_pts + (size_t)n_rays * (NT * 3);
    float* out_zs   = out_zall + (size_t)n_rays * NT;

    const int blocks = (n_rays + WPB - 1) / WPB;
    importance_sampler_kernel<<<blocks, 256>>>(rays_o, rays_d, z_vals, weights,
                                               out_pts, out_zall, out_zs, n_rays);
}

// round 7
// speedup vs baseline: 1.1903x; 1.1903x over previous
#include <cuda_runtime.h>

// NeRF importance sampler (R5 structure + de-staged phase 5):
//   inputs : rays_o[N,3], rays_d[N,3], z_vals[N,64] (sorted), weights[N,64]
//   outputs: pts[N,192,3] | z_all[N,192] | z_samples[N,128]  (flat concat)
//
// One warp per ray, 8 warps/block, 512-float shared scratch per warp:
//   [0,64)=zv [64,128)=cdf(63+inf sentinel) [128,192)=mid [192,320)=zs
//   [320,512)=zal
// Searches use the branchless pow2-count form (exact, never reads OOB).
// Phase 5 computes each output float4 directly from zal (2 scalar LDS + 6 FMA
// + 3-way select) with fully coalesced STG.128 — no shared staging.

#define NS   64
#define NI   128
#define NT   192
#define WPB  8

__global__ __launch_bounds__(256, 8)
void importance_sampler_kernel(const float* __restrict__ rays_o,
                               const float* __restrict__ rays_d,
                               const float* __restrict__ z_vals,
                               const float* __restrict__ weights,
                               float* __restrict__ out_pts,    // [N,192,3]
                               float* __restrict__ out_zall,   // [N,192]
                               float* __restrict__ out_zs,     // [N,128]
                               int n_rays)
{
    __shared__ __align__(16) float sbuf[WPB][512];

    const int warp = threadIdx.x >> 5;
    const int lane = threadIdx.x & 31;
    const int ray  = blockIdx.x * WPB + warp;
    if (ray >= n_rays) return;

    float* buf = sbuf[warp];
    float* zv  = buf;          // 64
    float* cdf = buf + 64;     // 64 (63 real + sentinel)
    float* mid = buf + 128;    // 63 used
    float* zs  = buf + 192;    // 128
    float* zal = buf + 320;    // 192

    // ---- Phase 1: load z_vals (float2) + build cdf ------------------------
    const float2 z2 = ((const float2*)(z_vals + (size_t)ray * NS))[lane];
    ((float2*)zv)[lane] = z2;

    const float2 w2 = ((const float2*)(weights + (size_t)ray * NS))[lane];
    const float wnx = __shfl_down_sync(0xffffffffu, w2.x, 1);   // wrow[2l+2]

    // w[j] = weights[j+1] + 1e-5, j = 0..61 -> lane l<=30 owns j=2l, 2l+1
    float wa = 0.f, wb = 0.f;
    if (lane < 31) {
        wa = w2.y + 1e-5f;
        wb = wnx  + 1e-5f;
    }
    const float local = wa + wb;
    float s = local;
    #pragma unroll
    for (int off = 1; off < 32; off <<= 1) {
        float up = __shfl_up_sync(0xffffffffu, s, off);
        if (lane >= off) s += up;
    }
    const float inv_total = 1.0f / __shfl_sync(0xffffffffu, s, 31);
    const float excl = s - local;

    if (lane == 0) cdf[0] = 0.f;
    if (lane < 31) {
        cdf[2 * lane + 1] = (excl + wa) * inv_total;
        cdf[2 * lane + 2] = (excl + local) * inv_total;
    } else {
        cdf[63] = 3.402823466e+38f;    // sentinel: never counted by <= u
    }

    // ---- Phase 2: z_mid[k] = 0.5*(zv[k]+zv[k+1]), k = 0..62 ---------------
    const float znx = __shfl_down_sync(0xffffffffu, z2.x, 1);   // zv[2l+2]
    mid[2 * lane] = 0.5f * (z2.x + z2.y);                       // mid[62] at l=31
    if (lane < 31) mid[2 * lane + 1] = 0.5f * (z2.y + znx);
    __syncwarp();

    // ---- Phase 3: 128 inverse-CDF samples (4 per lane) --------------------
    float* ozs = out_zs + (size_t)ray * NI;
    float vreg[4];
    int   loreg[4];
    #pragma unroll
    for (int t = 0; t < 4; t++) {
        const int i = lane + 32 * t;
        const float u = (float)i * (1.0f / 127.0f);
        // #{cdf[k] <= u} over padded n=64; sentinel keeps count <= 63
        int lo = 0;
        #pragma unroll
        for (int step = 32; step > 0; step >>= 1)
            if (cdf[lo + step - 1] <= u) lo += step;
        const int below = lo - 1;                  // lo >= 1 (cdf[0]=0<=u)
        const int above = min(lo, 62);
        const float cb = cdf[below];
        float denom = cdf[above] - cb;
        if (denom < 1e-5f) denom = 1.0f;
        const float tt = (u - cb) / denom;
        const float bb = mid[below];
        const float v  = fmaf(tt, mid[above] - bb, bb);
        zs[i]    = v;
        ozs[i]   = v;                              // coalesced STG.32
        vreg[t]  = v;
        loreg[t] = lo;
    }
    __syncwarp();

    // ---- Phase 4: rank-merge into zal -------------------------------------
    // zs[j] -> pos = j + #{zv <= v}; linear from cnt=min(lo,NS) is exact.
    #pragma unroll
    for (int t = 0; t < 4; t++) {
        const int j = lane + 32 * t;
        const float v = vreg[t];
        int cnt = min(loreg[t], NS);
        while (cnt < NS && zv[cnt] <= v) cnt++;
        zal[j + cnt] = v;
    }
    // zv[i] -> pos = i + #{zs < v}; count==128 handled explicitly.
    #pragma unroll
    for (int t = 0; t < 2; t++) {
        const int i = 2 * lane + t;
        const float v = t ? z2.y : z2.x;
        int pos;
        if (zs[NI - 1] < v) {
            pos = NI;
        } else {
            pos = 0;
            #pragma unroll
            for (int step = 64; step > 0; step >>= 1)
                if (zs[pos + step - 1] < v) pos += step;
        }
        zal[i + pos] = v;
    }
    __syncwarp();

    // ---- z_all out (float4, coalesced) ------------------------------------
    {
        float4* a4 = (float4*)(out_zall + (size_t)ray * NT);   // 48 x float4
        a4[lane] = ((const float4*)zal)[lane];
        if (lane < 16) a4[32 + lane] = ((const float4*)zal)[32 + lane];
    }

    // ---- Phase 5: pts directly from zal, fully coalesced STG.128 ----------
    const float ox = rays_o[3 * (size_t)ray + 0];
    const float oy = rays_o[3 * (size_t)ray + 1];
    const float oz = rays_o[3 * (size_t)ray + 2];
    const float dx = rays_d[3 * (size_t)ray + 0];
    const float dy = rays_d[3 * (size_t)ray + 1];
    const float dz = rays_d[3 * (size_t)ray + 2];

    float4* o4 = (float4*)(out_pts + (size_t)ray * (NT * 3));  // 144 x float4
    #pragma unroll
    for (int t = 0; t < 5; t++) {
        if (t < 4 || lane < 16) {
            const int m  = lane + 32 * t;          // output float4 id, 0..143
            const int r  = m % 3;                  // == (4m)%3 since 4 = 1 mod 3
            const int ka = (4 * m - r) / 3;        // first point touched
            const float za = zal[ka];
            const float zb = zal[ka + 1];          // ka+1 <= 191
            const float Ax = fmaf(dx, za, ox);
            const float Ay = fmaf(dy, za, oy);
            const float Az = fmaf(dz, za, oz);
            const float Bx = fmaf(dx, zb, ox);
            const float By = fmaf(dy, zb, oy);
            const float Bz = fmaf(dz, zb, oz);
            float4 o;
            if (r == 0)      o = make_float4(Ax, Ay, Az, Bx);
            else if (r == 1) o = make_float4(Ay, Az, Bx, By);
            else             o = make_float4(Az, Bx, By, Bz);
            o4[m] = o;                              // coalesced
        }
    }
}

extern "C" void kernel_launch(void* const* d_in, const int* in_sizes, int n_in,
                              void* d_out, int out_size)
{
    const float* rays_o  = (const float*)d_in[0];
    const float* rays_d  = (const float*)d_in[1];
    const float* z_vals  = (const float*)d_in[2];
    const float* weights = (const float*)d_in[3];

    const int n_rays = in_sizes[0] / 3;

    float* out_pts  = (float*)d_out;
    float* out_zall = out_pts + (size_t)n_rays * (NT * 3);
    float* out_zs   = out_zall + (size_t)n_rays * NT;

    const int blocks = (n_rays + WPB - 1) / WPB;
    importance_sampler_kernel<<<blocks, 256>>>(rays_o, rays_d, z_vals, weights,
                                               out_pts, out_zall, out_zs, n_rays);
}